// round 2
// baseline (speedup 1.0000x reference)
#include <cuda_runtime.h>
#include <cuda_bf16.h>
#include <cstdint>

#define TOKENS 8192
#define INF    4096
#define OUTF   4096
#define KTOT   (2 * INF)   // [x_hi | x_lo] concatenated along K

// Scratch (no allocations allowed in kernel_launch): module-level device globals.
__device__ __nv_bfloat16 g_Wb[(size_t)OUTF * INF];          // 32 MB
__device__ __nv_bfloat16 g_Xs[(size_t)TOKENS * KTOT];       // 128 MB
__device__ int g_w_is_i8;                                    // weight dtype flag

// ---------------------------------------------------------------------------
// Preprocess 0: detect whether the weight buffer is packed int8 or int32.
// If int32, every word is in [-2, 1]. If int8 (bytes FE/FF/00/01), a sampled
// int32 word is outside [-2,1] with overwhelming probability across 4K samples.
// Samples stay within the first 4M words (16 MB), in-bounds for both layouts.
// ---------------------------------------------------------------------------
__global__ void detect_w_kernel(const int* __restrict__ w32) {
    __shared__ int bad;
    if (threadIdx.x == 0) bad = 0;
    __syncthreads();
    for (int i = threadIdx.x; i < 4096; i += 256) {
        int v = w32[(size_t)i * 1000 + 3];   // max idx ~4,095,003 < 4,194,304
        if (v < -2 || v > 1) bad = 1;
    }
    __syncthreads();
    if (threadIdx.x == 0) g_w_is_i8 = bad;
}

// ---------------------------------------------------------------------------
// Preprocess 1: weights {-2,-1,0,1} (int8 OR int32) -> bf16 (exact)
// ---------------------------------------------------------------------------
__global__ void convert_w_kernel(const void* __restrict__ wq) {
    size_t i = (size_t)blockIdx.x * blockDim.x + threadIdx.x;   // one 4-elem group
    size_t total4 = (size_t)OUTF * INF / 4;
    if (i >= total4) return;
    int v0, v1, v2, v3;
    if (g_w_is_i8) {
        char4 v = reinterpret_cast<const char4*>(wq)[i];
        v0 = v.x; v1 = v.y; v2 = v.z; v3 = v.w;
    } else {
        int4 v = reinterpret_cast<const int4*>(wq)[i];
        v0 = v.x; v1 = v.y; v2 = v.z; v3 = v.w;
    }
    __nv_bfloat162 p0, p1;
    p0.x = __float2bfloat16_rn((float)v0);
    p0.y = __float2bfloat16_rn((float)v1);
    p1.x = __float2bfloat16_rn((float)v2);
    p1.y = __float2bfloat16_rn((float)v3);
    reinterpret_cast<__nv_bfloat162*>(g_Wb)[i * 2 + 0] = p0;
    reinterpret_cast<__nv_bfloat162*>(g_Wb)[i * 2 + 1] = p1;
}

// ---------------------------------------------------------------------------
// Preprocess 2: fp32 x -> [x_hi | x_lo] bf16 split, row layout [TOKENS][2*INF]
// ---------------------------------------------------------------------------
__global__ void split_x_kernel(const float* __restrict__ x) {
    size_t i = (size_t)blockIdx.x * blockDim.x + threadIdx.x;   // one float4 per thread
    size_t total4 = (size_t)TOKENS * INF / 4;
    if (i >= total4) return;
    float4 v = reinterpret_cast<const float4*>(x)[i];
    size_t base = i * 4;
    size_t row = base >> 12;           // / INF
    size_t col = base & (INF - 1);

    float f[4] = {v.x, v.y, v.z, v.w};
    __nv_bfloat16 h[4], l[4];
#pragma unroll
    for (int j = 0; j < 4; j++) {
        h[j] = __float2bfloat16_rn(f[j]);
        l[j] = __float2bfloat16_rn(f[j] - __bfloat162float(h[j]));
    }
    __nv_bfloat162 h0, h1, l0, l1;
    h0.x = h[0]; h0.y = h[1]; h1.x = h[2]; h1.y = h[3];
    l0.x = l[0]; l0.y = l[1]; l1.x = l[2]; l1.y = l[3];

    __nv_bfloat16* dst_hi = g_Xs + row * KTOT + col;
    __nv_bfloat16* dst_lo = dst_hi + INF;
    reinterpret_cast<__nv_bfloat162*>(dst_hi)[0] = h0;
    reinterpret_cast<__nv_bfloat162*>(dst_hi)[1] = h1;
    reinterpret_cast<__nv_bfloat162*>(dst_lo)[0] = l0;
    reinterpret_cast<__nv_bfloat162*>(dst_lo)[1] = l1;
}

// ---------------------------------------------------------------------------
// GEMM: C[8192,4096] = Xs[8192,8192] @ (Wb repeated)^T, epilogue scale*acc+bias
// ---------------------------------------------------------------------------
#define BM 128
#define BN 128
#define BK 32
#define PAD 40          // padded bf16 row length in smem (80B pitch, conflict-free ldmatrix)
#define KT  (KTOT / BK) // 256 k-iterations

__device__ __forceinline__ void load_tile(uint32_t sA, uint32_t sB,
                                          const __nv_bfloat16* Ag,
                                          const __nv_bfloat16* Bg,
                                          int kt, int buf, int tid) {
    int kk = kt * BK;
    int kb = kk & (INF - 1);
#pragma unroll
    for (int i = 0; i < 2; i++) {
        int c = tid + i * 256;
        int row = c >> 2;
        int grp = c & 3;
        uint32_t da = sA + (uint32_t)(buf * BM * PAD + row * PAD + grp * 8) * 2;
        const void* ga = Ag + (size_t)row * KTOT + kk + grp * 8;
        asm volatile("cp.async.cg.shared.global [%0], [%1], 16;\n" :: "r"(da), "l"(ga));
        uint32_t db = sB + (uint32_t)(buf * BN * PAD + row * PAD + grp * 8) * 2;
        const void* gb = Bg + (size_t)row * INF + kb + grp * 8;
        asm volatile("cp.async.cg.shared.global [%0], [%1], 16;\n" :: "r"(db), "l"(gb));
    }
    asm volatile("cp.async.commit_group;\n");
}

__global__ __launch_bounds__(256, 2) void gemm_kernel(const float* __restrict__ scale_p,
                                                      const float* __restrict__ bias,
                                                      float* __restrict__ out) {
    __shared__ __nv_bfloat16 As[2 * BM * PAD];
    __shared__ __nv_bfloat16 Bs[2 * BN * PAD];

    const int tid  = threadIdx.x;
    const int warp = tid >> 5;
    const int lane = tid & 31;
    const int wm   = warp & 1;      // warp tile: 64 (M) x 32 (N), 2x4 warp grid
    const int wn   = warp >> 1;
    const int bm   = blockIdx.y * BM;
    const int bn   = blockIdx.x * BN;

    const __nv_bfloat16* Ag = g_Xs + (size_t)bm * KTOT;
    const __nv_bfloat16* Bg = g_Wb + (size_t)bn * INF;

    const uint32_t sA = (uint32_t)__cvta_generic_to_shared(As);
    const uint32_t sB = (uint32_t)__cvta_generic_to_shared(Bs);

    float acc[4][4][4];
#pragma unroll
    for (int mt = 0; mt < 4; mt++)
#pragma unroll
        for (int nt = 0; nt < 4; nt++)
#pragma unroll
            for (int r = 0; r < 4; r++) acc[mt][nt][r] = 0.0f;

    load_tile(sA, sB, Ag, Bg, 0, 0, tid);

#pragma unroll 1
    for (int kt = 0; kt < KT; kt++) {
        const int buf = kt & 1;
        if (kt + 1 < KT) {
            load_tile(sA, sB, Ag, Bg, kt + 1, buf ^ 1, tid);
            asm volatile("cp.async.wait_group 1;\n");
        } else {
            asm volatile("cp.async.wait_group 0;\n");
        }
        __syncthreads();

#pragma unroll
        for (int ks = 0; ks < 2; ks++) {
            // A fragments: 4 m-tiles of 16x16
            uint32_t a[4][4];
#pragma unroll
            for (int mt = 0; mt < 4; mt++) {
                int row = wm * 64 + mt * 16 + (lane & 15);
                int col = ks * 16 + ((lane >> 4) << 3);
                uint32_t addr = sA + (uint32_t)(buf * BM * PAD + row * PAD + col) * 2;
                asm volatile(
                    "ldmatrix.sync.aligned.m8n8.x4.shared.b16 {%0,%1,%2,%3}, [%4];\n"
                    : "=r"(a[mt][0]), "=r"(a[mt][1]), "=r"(a[mt][2]), "=r"(a[mt][3])
                    : "r"(addr));
            }
            // B fragments: 4 n-tiles of 8 (two x4 loads, each covers 16 n-rows)
            uint32_t b[4][2];
#pragma unroll
            for (int np = 0; np < 2; np++) {
                int nrow = wn * 32 + np * 16 + ((lane >> 4) << 3) + (lane & 7);
                int kcol = ks * 16 + ((lane >> 3) & 1) * 8;
                uint32_t addr = sB + (uint32_t)(buf * BN * PAD + nrow * PAD + kcol) * 2;
                asm volatile(
                    "ldmatrix.sync.aligned.m8n8.x4.shared.b16 {%0,%1,%2,%3}, [%4];\n"
                    : "=r"(b[np * 2][0]), "=r"(b[np * 2][1]),
                      "=r"(b[np * 2 + 1][0]), "=r"(b[np * 2 + 1][1])
                    : "r"(addr));
            }
#pragma unroll
            for (int mt = 0; mt < 4; mt++)
#pragma unroll
                for (int nt = 0; nt < 4; nt++) {
                    asm volatile(
                        "mma.sync.aligned.m16n8k16.row.col.f32.bf16.bf16.f32 "
                        "{%0,%1,%2,%3}, {%4,%5,%6,%7}, {%8,%9}, {%0,%1,%2,%3};\n"
                        : "+f"(acc[mt][nt][0]), "+f"(acc[mt][nt][1]),
                          "+f"(acc[mt][nt][2]), "+f"(acc[mt][nt][3])
                        : "r"(a[mt][0]), "r"(a[mt][1]), "r"(a[mt][2]), "r"(a[mt][3]),
                          "r"(b[nt][0]), "r"(b[nt][1]));
                }
        }
        __syncthreads();
    }

    // Epilogue: y = scale * acc + bias
    const float s = __ldg(scale_p);
#pragma unroll
    for (int mt = 0; mt < 4; mt++) {
#pragma unroll
        for (int nt = 0; nt < 4; nt++) {
            int r0 = bm + wm * 64 + mt * 16 + (lane >> 2);
            int c  = bn + wn * 32 + nt * 8 + (lane & 3) * 2;
            float b0 = __ldg(bias + c);
            float b1 = __ldg(bias + c + 1);
            float2 v0 = make_float2(acc[mt][nt][0] * s + b0, acc[mt][nt][1] * s + b1);
            float2 v1 = make_float2(acc[mt][nt][2] * s + b0, acc[mt][nt][3] * s + b1);
            *reinterpret_cast<float2*>(out + (size_t)r0 * OUTF + c) = v0;
            *reinterpret_cast<float2*>(out + (size_t)(r0 + 8) * OUTF + c) = v1;
        }
    }
}

// ---------------------------------------------------------------------------
extern "C" void kernel_launch(void* const* d_in, const int* in_sizes, int n_in,
                              void* d_out, int out_size) {
    const float* x     = (const float*)d_in[0];
    const void*  wq    = d_in[1];
    const float* scale = (const float*)d_in[2];
    const float* bias  = (const float*)d_in[3];
    float*       out   = (float*)d_out;

    detect_w_kernel<<<1, 256>>>((const int*)wq);
    {
        size_t total4 = (size_t)OUTF * INF / 4;
        convert_w_kernel<<<(unsigned)((total4 + 255) / 256), 256>>>(wq);
    }
    {
        size_t total4 = (size_t)TOKENS * INF / 4;
        split_x_kernel<<<(unsigned)((total4 + 255) / 256), 256>>>(x);
    }
    {
        dim3 grid(OUTF / BN, TOKENS / BM);
        gemm_kernel<<<grid, 256>>>(scale, bias, out);
    }
}

// round 5
// speedup vs baseline: 1.8950x; 1.8950x over previous
#include <cuda_runtime.h>
#include <cuda_fp16.h>
#include <cstdint>

#define TOKENS 8192
#define INF    4096
#define OUTF   4096

// Scratch device globals (no allocations allowed).
__device__ __half g_Wh[(size_t)OUTF * INF];    // 32 MB
__device__ __half g_Xh[(size_t)TOKENS * INF];  // 64 MB
__device__ int g_w_is_i8;

// ---------------------------------------------------------------------------
// Preprocess 0: weight dtype detection (int8 vs int32 delivery)
// ---------------------------------------------------------------------------
__global__ void detect_w_kernel(const int* __restrict__ w32) {
    __shared__ int bad;
    if (threadIdx.x == 0) bad = 0;
    __syncthreads();
    for (int i = threadIdx.x; i < 4096; i += 256) {
        int v = w32[(size_t)i * 1000 + 3];
        if (v < -2 || v > 1) bad = 1;
    }
    __syncthreads();
    if (threadIdx.x == 0) g_w_is_i8 = bad;
}

// ---------------------------------------------------------------------------
// Preprocess 1: weights {-2,-1,0,1} (int8 OR int32) -> fp16 (exact)
// ---------------------------------------------------------------------------
__global__ void convert_w_kernel(const void* __restrict__ wq) {
    size_t i = (size_t)blockIdx.x * blockDim.x + threadIdx.x;
    size_t total4 = (size_t)OUTF * INF / 4;
    if (i >= total4) return;
    int v0, v1, v2, v3;
    if (g_w_is_i8) {
        char4 v = reinterpret_cast<const char4*>(wq)[i];
        v0 = v.x; v1 = v.y; v2 = v.z; v3 = v.w;
    } else {
        int4 v = reinterpret_cast<const int4*>(wq)[i];
        v0 = v.x; v1 = v.y; v2 = v.z; v3 = v.w;
    }
    __half2 p0, p1;
    p0.x = __float2half_rn((float)v0); p0.y = __float2half_rn((float)v1);
    p1.x = __float2half_rn((float)v2); p1.y = __float2half_rn((float)v3);
    reinterpret_cast<__half2*>(g_Wh)[i * 2 + 0] = p0;
    reinterpret_cast<__half2*>(g_Wh)[i * 2 + 1] = p1;
}

// ---------------------------------------------------------------------------
// Preprocess 2: fp32 x -> fp16
// ---------------------------------------------------------------------------
__global__ void convert_x_kernel(const float* __restrict__ x) {
    size_t i = (size_t)blockIdx.x * blockDim.x + threadIdx.x;
    size_t total4 = (size_t)TOKENS * INF / 4;
    if (i >= total4) return;
    float4 v = reinterpret_cast<const float4*>(x)[i];
    __half2 p0, p1;
    p0.x = __float2half_rn(v.x); p0.y = __float2half_rn(v.y);
    p1.x = __float2half_rn(v.z); p1.y = __float2half_rn(v.w);
    reinterpret_cast<__half2*>(g_Xh)[i * 2 + 0] = p0;
    reinterpret_cast<__half2*>(g_Xh)[i * 2 + 1] = p1;
}

// ---------------------------------------------------------------------------
// GEMM: C[8192,4096] = Xh @ Wh^T + epilogue.  BM=256 BN=128 BK=64, 512 thr.
// Warp grid 4(m) x 4(n); warp tile 64x32 via m16n8k16 fp16->f32 mma.sync.
// ---------------------------------------------------------------------------
#define BM 256
#define BN 128
#define BK 64
#define KT (INF / BK)        // 64 outer iterations
#define PADE 72              // smem row pitch in fp16 elems (144 B)
#define PB   (PADE * 2)      // 144 bytes
#define A_STG (BM * PB)      // 36864
#define B_STG (BN * PB)      // 18432
#define STG   (A_STG + B_STG)
#define SMEM_TOTAL (2 * STG) // 110592 B

__device__ __forceinline__ void load_tile(uint32_t sbase,
                                          const __half* Ag, const __half* Bg,
                                          int kt, int buf, int tid) {
    const int kk = kt * BK;
    const uint32_t d0 = sbase + buf * STG;
#pragma unroll
    for (int i = 0; i < 6; i++) {
        int c = tid + i * 512;
        const void* src;
        uint32_t dst;
        if (i < 4) {                         // A: 256 rows x 8 segs = 2048 chunks
            int row = c >> 3, seg = c & 7;
            src = Ag + (size_t)row * INF + kk + seg * 8;
            dst = d0 + row * PB + seg * 16;
        } else {                             // B: 128 rows x 8 segs = 1024 chunks
            int o = c - 2048;
            int row = o >> 3, seg = o & 7;
            src = Bg + (size_t)row * INF + kk + seg * 8;
            dst = d0 + A_STG + row * PB + seg * 16;
        }
        asm volatile("cp.async.cg.shared.global [%0], [%1], 16;\n" :: "r"(dst), "l"(src));
    }
    asm volatile("cp.async.commit_group;\n");
}

__global__ __launch_bounds__(512, 1) void gemm_kernel(const float* __restrict__ scale_p,
                                                      const float* __restrict__ bias,
                                                      float* __restrict__ out) {
    extern __shared__ char smem[];
    uint32_t sbase;
    asm("{ .reg .u64 t; cvta.to.shared.u64 t, %1; cvt.u32.u64 %0, t; }"
        : "=r"(sbase) : "l"(smem));

    const int tid  = threadIdx.x;
    const int warp = tid >> 5;
    const int lane = tid & 31;
    const int wm   = warp & 3;       // 4 m-warps: 64 rows each
    const int wn   = warp >> 2;      // 4 n-warps: 32 cols each
    const int bm   = blockIdx.y * BM;
    const int bn   = blockIdx.x * BN;

    const __half* Ag = g_Xh + (size_t)bm * INF;
    const __half* Bg = g_Wh + (size_t)bn * INF;

    float acc[4][4][4];
#pragma unroll
    for (int mt = 0; mt < 4; mt++)
#pragma unroll
        for (int nt = 0; nt < 4; nt++)
#pragma unroll
            for (int r = 0; r < 4; r++) acc[mt][nt][r] = 0.0f;

    load_tile(sbase, Ag, Bg, 0, 0, tid);

#pragma unroll 1
    for (int kt = 0; kt < KT; kt++) {
        const int buf = kt & 1;
        if (kt + 1 < KT) {
            load_tile(sbase, Ag, Bg, kt + 1, buf ^ 1, tid);
            asm volatile("cp.async.wait_group 1;\n");
        } else {
            asm volatile("cp.async.wait_group 0;\n");
        }
        __syncthreads();

        const uint32_t aBase = sbase + buf * STG;
        const uint32_t bBase = aBase + A_STG;
#pragma unroll
        for (int ks = 0; ks < 4; ks++) {
            uint32_t a[4][4];
#pragma unroll
            for (int mt = 0; mt < 4; mt++) {
                int row = wm * 64 + mt * 16 + (lane & 15);
                int col = ks * 16 + ((lane >> 4) << 3);
                uint32_t addr = aBase + (uint32_t)row * PB + (uint32_t)col * 2;
                asm volatile(
                    "ldmatrix.sync.aligned.m8n8.x4.shared.b16 {%0,%1,%2,%3}, [%4];\n"
                    : "=r"(a[mt][0]), "=r"(a[mt][1]), "=r"(a[mt][2]), "=r"(a[mt][3])
                    : "r"(addr));
            }
            uint32_t b[4][2];
#pragma unroll
            for (int np = 0; np < 2; np++) {
                int nrow = wn * 32 + np * 16 + ((lane >> 4) << 3) + (lane & 7);
                int kcol = ks * 16 + ((lane >> 3) & 1) * 8;
                uint32_t addr = bBase + (uint32_t)nrow * PB + (uint32_t)kcol * 2;
                asm volatile(
                    "ldmatrix.sync.aligned.m8n8.x4.shared.b16 {%0,%1,%2,%3}, [%4];\n"
                    : "=r"(b[np * 2][0]), "=r"(b[np * 2][1]),
                      "=r"(b[np * 2 + 1][0]), "=r"(b[np * 2 + 1][1])
                    : "r"(addr));
            }
#pragma unroll
            for (int mt = 0; mt < 4; mt++)
#pragma unroll
                for (int nt = 0; nt < 4; nt++) {
                    asm volatile(
                        "mma.sync.aligned.m16n8k16.row.col.f32.f16.f16.f32 "
                        "{%0,%1,%2,%3}, {%4,%5,%6,%7}, {%8,%9}, {%0,%1,%2,%3};\n"
                        : "+f"(acc[mt][nt][0]), "+f"(acc[mt][nt][1]),
                          "+f"(acc[mt][nt][2]), "+f"(acc[mt][nt][3])
                        : "r"(a[mt][0]), "r"(a[mt][1]), "r"(a[mt][2]), "r"(a[mt][3]),
                          "r"(b[nt][0]), "r"(b[nt][1]));
                }
        }
        __syncthreads();
    }

    // Epilogue: y = scale * acc + bias
    const float s = __ldg(scale_p);
#pragma unroll
    for (int mt = 0; mt < 4; mt++) {
#pragma unroll
        for (int nt = 0; nt < 4; nt++) {
            int r0 = bm + wm * 64 + mt * 16 + (lane >> 2);
            int c  = bn + wn * 32 + nt * 8 + (lane & 3) * 2;
            float b0 = __ldg(bias + c);
            float b1 = __ldg(bias + c + 1);
            float2 v0 = make_float2(acc[mt][nt][0] * s + b0, acc[mt][nt][1] * s + b1);
            float2 v1 = make_float2(acc[mt][nt][2] * s + b0, acc[mt][nt][3] * s + b1);
            *reinterpret_cast<float2*>(out + (size_t)r0 * OUTF + c) = v0;
            *reinterpret_cast<float2*>(out + (size_t)(r0 + 8) * OUTF + c) = v1;
        }
    }
}

// ---------------------------------------------------------------------------
extern "C" void kernel_launch(void* const* d_in, const int* in_sizes, int n_in,
                              void* d_out, int out_size) {
    const float* x     = (const float*)d_in[0];
    const void*  wq    = d_in[1];
    const float* scale = (const float*)d_in[2];
    const float* bias  = (const float*)d_in[3];
    float*       out   = (float*)d_out;

    detect_w_kernel<<<1, 256>>>((const int*)wq);
    convert_w_kernel<<<(unsigned)((size_t)OUTF * INF / 4 / 256), 256>>>(wq);
    convert_x_kernel<<<(unsigned)((size_t)TOKENS * INF / 4 / 256), 256>>>(x);

    cudaFuncSetAttribute(gemm_kernel, cudaFuncAttributeMaxDynamicSharedMemorySize, SMEM_TOTAL);
    dim3 grid(OUTF / BN, TOKENS / BM);
    gemm_kernel<<<grid, 512, SMEM_TOTAL>>>(scale, bias, out);
}

// round 6
// speedup vs baseline: 2.0991x; 1.1077x over previous
#include <cuda_runtime.h>
#include <cuda_fp16.h>
#include <cstdint>

#define TOKENS 8192
#define INF    4096
#define OUTF   4096

// Scratch device globals (no allocations allowed).
__device__ __half g_Wh[(size_t)OUTF * INF];    // 32 MB
__device__ __half g_Xh[(size_t)TOKENS * INF];  // 64 MB
__device__ int g_w_is_i8;

// ---------------------------------------------------------------------------
// Preprocess 0: weight dtype detection (int8 vs int32 delivery)
// ---------------------------------------------------------------------------
__global__ void detect_w_kernel(const int* __restrict__ w32) {
    __shared__ int bad;
    if (threadIdx.x == 0) bad = 0;
    __syncthreads();
    for (int i = threadIdx.x; i < 4096; i += 256) {
        int v = w32[(size_t)i * 1000 + 3];
        if (v < -2 || v > 1) bad = 1;
    }
    __syncthreads();
    if (threadIdx.x == 0) g_w_is_i8 = bad;
}

// ---------------------------------------------------------------------------
// Preprocess 1: weights {-2,-1,0,1} (int8 OR int32) -> fp16 (exact)
// ---------------------------------------------------------------------------
__global__ void convert_w_kernel(const void* __restrict__ wq) {
    size_t i = (size_t)blockIdx.x * blockDim.x + threadIdx.x;
    size_t total4 = (size_t)OUTF * INF / 4;
    if (i >= total4) return;
    int v0, v1, v2, v3;
    if (g_w_is_i8) {
        char4 v = reinterpret_cast<const char4*>(wq)[i];
        v0 = v.x; v1 = v.y; v2 = v.z; v3 = v.w;
    } else {
        int4 v = reinterpret_cast<const int4*>(wq)[i];
        v0 = v.x; v1 = v.y; v2 = v.z; v3 = v.w;
    }
    __half2 p0, p1;
    p0.x = __float2half_rn((float)v0); p0.y = __float2half_rn((float)v1);
    p1.x = __float2half_rn((float)v2); p1.y = __float2half_rn((float)v3);
    reinterpret_cast<__half2*>(g_Wh)[i * 2 + 0] = p0;
    reinterpret_cast<__half2*>(g_Wh)[i * 2 + 1] = p1;
}

// ---------------------------------------------------------------------------
// Preprocess 2: fp32 x -> fp16
// ---------------------------------------------------------------------------
__global__ void convert_x_kernel(const float* __restrict__ x) {
    size_t i = (size_t)blockIdx.x * blockDim.x + threadIdx.x;
    size_t total4 = (size_t)TOKENS * INF / 4;
    if (i >= total4) return;
    float4 v = reinterpret_cast<const float4*>(x)[i];
    __half2 p0, p1;
    p0.x = __float2half_rn(v.x); p0.y = __float2half_rn(v.y);
    p1.x = __float2half_rn(v.z); p1.y = __float2half_rn(v.w);
    reinterpret_cast<__half2*>(g_Xh)[i * 2 + 0] = p0;
    reinterpret_cast<__half2*>(g_Xh)[i * 2 + 1] = p1;
}

// ---------------------------------------------------------------------------
// GEMM: C = Xh @ Wh^T + epilogue.  BM=128 BN=128 BK=64, 256 thr, 2 CTAs/SM,
// 3-stage cp.async pipeline, ONE __syncthreads per k-iteration.
// Warp grid 2(m) x 4(n); warp tile 64x32 via m16n8k16 fp16->f32 mma.sync.
// ---------------------------------------------------------------------------
#define BM 128
#define BN 128
#define BK 64
#define KT (INF / BK)        // 64 outer iterations
#define STAGES 3
#define PADE 72              // smem row pitch in fp16 elems (144 B)
#define PB   (PADE * 2)      // 144 bytes
#define A_STG (BM * PB)      // 18432
#define B_STG (BN * PB)      // 18432
#define STG   (A_STG + B_STG)          // 36864
#define SMEM_TOTAL (STAGES * STG)      // 110592 B per CTA

__device__ __forceinline__ void load_tile(uint32_t sbase,
                                          const __half* Ag, const __half* Bg,
                                          int kt, int stage, int tid) {
    const int kk = kt * BK;
    const uint32_t d0 = sbase + stage * STG;
#pragma unroll
    for (int i = 0; i < 8; i++) {
        int c = tid + i * 256;
        const void* src;
        uint32_t dst;
        if (i < 4) {                         // A: 128 rows x 8 segs = 1024 chunks
            int row = c >> 3, seg = c & 7;
            src = Ag + (size_t)row * INF + kk + seg * 8;
            dst = d0 + row * PB + seg * 16;
        } else {                             // B: 128 rows x 8 segs = 1024 chunks
            int o = c - 1024;
            int row = o >> 3, seg = o & 7;
            src = Bg + (size_t)row * INF + kk + seg * 8;
            dst = d0 + A_STG + row * PB + seg * 16;
        }
        asm volatile("cp.async.cg.shared.global [%0], [%1], 16;\n" :: "r"(dst), "l"(src));
    }
    asm volatile("cp.async.commit_group;\n");
}

__global__ __launch_bounds__(256, 2) void gemm_kernel(const float* __restrict__ scale_p,
                                                      const float* __restrict__ bias,
                                                      float* __restrict__ out) {
    extern __shared__ char smem[];
    uint32_t sbase;
    asm("{ .reg .u64 t; cvta.to.shared.u64 t, %1; cvt.u32.u64 %0, t; }"
        : "=r"(sbase) : "l"(smem));

    const int tid  = threadIdx.x;
    const int warp = tid >> 5;
    const int lane = tid & 31;
    const int wm   = warp & 1;       // 2 m-warps: 64 rows each
    const int wn   = warp >> 1;      // 4 n-warps: 32 cols each
    const int bm   = blockIdx.y * BM;
    const int bn   = blockIdx.x * BN;

    const __half* Ag = g_Xh + (size_t)bm * INF;
    const __half* Bg = g_Wh + (size_t)bn * INF;

    float acc[4][4][4];
#pragma unroll
    for (int mt = 0; mt < 4; mt++)
#pragma unroll
        for (int nt = 0; nt < 4; nt++)
#pragma unroll
            for (int r = 0; r < 4; r++) acc[mt][nt][r] = 0.0f;

    // Prologue: stages 0,1 <- chunks 0,1
    load_tile(sbase, Ag, Bg, 0, 0, tid);
    load_tile(sbase, Ag, Bg, 1, 1, tid);

#pragma unroll 1
    for (int kt = 0; kt < KT; kt++) {
        if (kt == KT - 1) asm volatile("cp.async.wait_group 0;\n");
        else              asm volatile("cp.async.wait_group 1;\n");
        __syncthreads();

        // Refill the stage consumed last iteration with chunk kt+2.
        if (kt + 2 < KT) {
            int ls = (kt + 2) % STAGES;
            load_tile(sbase, Ag, Bg, kt + 2, ls, tid);
        }

        const int s = kt % STAGES;
        const uint32_t aBase = sbase + s * STG;
        const uint32_t bBase = aBase + A_STG;
#pragma unroll
        for (int ks = 0; ks < 4; ks++) {
            uint32_t a[4][4];
#pragma unroll
            for (int mt = 0; mt < 4; mt++) {
                int row = wm * 64 + mt * 16 + (lane & 15);
                int col = ks * 16 + ((lane >> 4) << 3);
                uint32_t addr = aBase + (uint32_t)row * PB + (uint32_t)col * 2;
                asm volatile(
                    "ldmatrix.sync.aligned.m8n8.x4.shared.b16 {%0,%1,%2,%3}, [%4];\n"
                    : "=r"(a[mt][0]), "=r"(a[mt][1]), "=r"(a[mt][2]), "=r"(a[mt][3])
                    : "r"(addr));
            }
            uint32_t b[4][2];
#pragma unroll
            for (int np = 0; np < 2; np++) {
                int nrow = wn * 32 + np * 16 + ((lane >> 4) << 3) + (lane & 7);
                int kcol = ks * 16 + ((lane >> 3) & 1) * 8;
                uint32_t addr = bBase + (uint32_t)nrow * PB + (uint32_t)kcol * 2;
                asm volatile(
                    "ldmatrix.sync.aligned.m8n8.x4.shared.b16 {%0,%1,%2,%3}, [%4];\n"
                    : "=r"(b[np * 2][0]), "=r"(b[np * 2][1]),
                      "=r"(b[np * 2 + 1][0]), "=r"(b[np * 2 + 1][1])
                    : "r"(addr));
            }
#pragma unroll
            for (int mt = 0; mt < 4; mt++)
#pragma unroll
                for (int nt = 0; nt < 4; nt++) {
                    asm volatile(
                        "mma.sync.aligned.m16n8k16.row.col.f32.f16.f16.f32 "
                        "{%0,%1,%2,%3}, {%4,%5,%6,%7}, {%8,%9}, {%0,%1,%2,%3};\n"
                        : "+f"(acc[mt][nt][0]), "+f"(acc[mt][nt][1]),
                          "+f"(acc[mt][nt][2]), "+f"(acc[mt][nt][3])
                        : "r"(a[mt][0]), "r"(a[mt][1]), "r"(a[mt][2]), "r"(a[mt][3]),
                          "r"(b[nt][0]), "r"(b[nt][1]));
                }
        }
    }

    // Epilogue: y = scale * acc + bias
    const float s = __ldg(scale_p);
#pragma unroll
    for (int mt = 0; mt < 4; mt++) {
#pragma unroll
        for (int nt = 0; nt < 4; nt++) {
            int r0 = bm + wm * 64 + mt * 16 + (lane >> 2);
            int c  = bn + wn * 32 + nt * 8 + (lane & 3) * 2;
            float b0 = __ldg(bias + c);
            float b1 = __ldg(bias + c + 1);
            float2 v0 = make_float2(acc[mt][nt][0] * s + b0, acc[mt][nt][1] * s + b1);
            float2 v1 = make_float2(acc[mt][nt][2] * s + b0, acc[mt][nt][3] * s + b1);
            *reinterpret_cast<float2*>(out + (size_t)r0 * OUTF + c) = v0;
            *reinterpret_cast<float2*>(out + (size_t)(r0 + 8) * OUTF + c) = v1;
        }
    }
}

// ---------------------------------------------------------------------------
extern "C" void kernel_launch(void* const* d_in, const int* in_sizes, int n_in,
                              void* d_out, int out_size) {
    const float* x     = (const float*)d_in[0];
    const void*  wq    = d_in[1];
    const float* scale = (const float*)d_in[2];
    const float* bias  = (const float*)d_in[3];
    float*       out   = (float*)d_out;

    detect_w_kernel<<<1, 256>>>((const int*)wq);
    convert_w_kernel<<<(unsigned)((size_t)OUTF * INF / 4 / 256), 256>>>(wq);
    convert_x_kernel<<<(unsigned)((size_t)TOKENS * INF / 4 / 256), 256>>>(x);

    cudaFuncSetAttribute(gemm_kernel, cudaFuncAttributeMaxDynamicSharedMemorySize, SMEM_TOTAL);
    dim3 grid(OUTF / BN, TOKENS / BM);
    gemm_kernel<<<grid, 256, SMEM_TOTAL>>>(scale, bias, out);
}